// round 2
// baseline (speedup 1.0000x reference)
#include <cuda_runtime.h>

#define QTILE 32
#define KN 16
#define NP 15
#define CIN 64
#define COUT 128
#define NTHREADS 256

__global__ __launch_bounds__(NTHREADS, 1)
void kpconv_kernel(const float* __restrict__ query,
                   const float* __restrict__ support,
                   const int*   __restrict__ nidx,
                   const float* __restrict__ feats,
                   const float* __restrict__ W,
                   const float* __restrict__ kp,
                   float* __restrict__ out)
{
    extern __shared__ float smem[];
    float* s_feats = smem;                              // 32768
    float* s_infl  = s_feats + QTILE * KN * CIN;        //  8192
    float* s_agg   = s_infl  + QTILE * KN * 16;         //  2048
    float* s_w     = s_agg   + QTILE * CIN;             //  8192
    float* s_kp    = s_w     + CIN * COUT;              //    48
    float* s_q     = s_kp + 48;                         //    96
    int*   s_nidx  = (int*)(s_q + 96);                  //   512 ints

    const int tid = threadIdx.x;
    const int n0  = blockIdx.x * QTILE;

    // ---- stage 0: indices, kernel points, query coords ----
    for (int i = tid; i < QTILE * KN; i += NTHREADS)
        s_nidx[i] = nidx[n0 * KN + i];
    if (tid < NP * 3)    s_kp[tid] = kp[tid];
    if (tid < QTILE * 3) s_q[tid]  = query[n0 * 3 + tid];
    __syncthreads();

    // ---- stage 1: gather neighbor features (float4, L2-resident) ----
    for (int i = tid; i < QTILE * KN * (CIN / 4); i += NTHREADS) {
        int pair = i >> 4;      // / (CIN/4)
        int c4   = i & 15;
        int m    = s_nidx[pair];
        float4 v = __ldg((const float4*)(feats + (size_t)m * CIN) + c4);
        ((float4*)s_feats)[i] = v;
    }

    // ---- stage 2: influences infl[q][k][p] = max(0, 1 - |rel - kp_p|) ----
    for (int pair = tid; pair < QTILE * KN; pair += NTHREADS) {
        int q = pair >> 4;
        int m = s_nidx[pair];
        float rx = support[m * 3 + 0] - s_q[q * 3 + 0];
        float ry = support[m * 3 + 1] - s_q[q * 3 + 1];
        float rz = support[m * 3 + 2] - s_q[q * 3 + 2];
        #pragma unroll
        for (int p = 0; p < NP; p++) {
            float dx = rx - s_kp[p * 3 + 0];
            float dy = ry - s_kp[p * 3 + 1];
            float dz = rz - s_kp[p * 3 + 2];
            float d  = sqrtf(fmaf(dx, dx, fmaf(dy, dy, dz * dz)));
            s_infl[pair * 16 + p] = fmaxf(1.0f - d, 0.0f);
        }
    }
    __syncthreads();   // <<< FIX: s_feats/s_infl must be complete before agg reads

    // ---- main loop over kernel points ----
    float acc[4][4];
    #pragma unroll
    for (int i = 0; i < 4; i++)
        #pragma unroll
        for (int j = 0; j < 4; j++) acc[i][j] = 0.0f;

    const int rg = tid >> 5;          // warp id -> row group (4 rows)
    const int cg = tid & 31;          // lane    -> col group (4 cols)
    const int r0 = rg << 2;
    const int o0 = cg << 2;

    const int myq  = tid >> 3;        // agg mapping: 1 query row,
    const int myc0 = (tid & 7) << 3;  // 8 consecutive channels per thread

    for (int p = 0; p < NP; p++) {
        // prefetch W[p] into registers (hides L2 latency behind agg math)
        float4 wreg[8];
        const float4* Wp = (const float4*)(W + p * CIN * COUT);
        #pragma unroll
        for (int j = 0; j < 8; j++)
            wreg[j] = __ldg(Wp + tid + j * NTHREADS);

        // aggregate: a[c] = sum_k infl[q][k][p] * feat[q][k][c]
        float a[8];
        #pragma unroll
        for (int j = 0; j < 8; j++) a[j] = 0.0f;
        const float* fr = s_feats + myq * KN * CIN + myc0;
        const float* ir = s_infl  + myq * KN * 16 + p;
        #pragma unroll
        for (int k = 0; k < KN; k++) {
            float in = ir[k * 16];
            float4 f0 = *(const float4*)(fr + k * CIN);
            float4 f1 = *(const float4*)(fr + k * CIN + 4);
            a[0] = fmaf(in, f0.x, a[0]);
            a[1] = fmaf(in, f0.y, a[1]);
            a[2] = fmaf(in, f0.z, a[2]);
            a[3] = fmaf(in, f0.w, a[3]);
            a[4] = fmaf(in, f1.x, a[4]);
            a[5] = fmaf(in, f1.y, a[5]);
            a[6] = fmaf(in, f1.z, a[6]);
            a[7] = fmaf(in, f1.w, a[7]);
        }

        __syncthreads();   // previous p's GEMM finished reading s_agg/s_w
        #pragma unroll
        for (int j = 0; j < 8; j++)
            s_agg[myq * CIN + myc0 + j] = a[j];
        #pragma unroll
        for (int j = 0; j < 8; j++)
            ((float4*)s_w)[tid + j * NTHREADS] = wreg[j];
        __syncthreads();

        // GEMM accumulate: out[32x128] += agg[32x64] @ W[p][64x128]
        #pragma unroll 16
        for (int c = 0; c < CIN; c++) {
            float4 w = *(const float4*)(s_w + c * COUT + o0);
            float a0 = s_agg[(r0 + 0) * CIN + c];
            float a1 = s_agg[(r0 + 1) * CIN + c];
            float a2 = s_agg[(r0 + 2) * CIN + c];
            float a3 = s_agg[(r0 + 3) * CIN + c];
            acc[0][0] = fmaf(a0, w.x, acc[0][0]);
            acc[0][1] = fmaf(a0, w.y, acc[0][1]);
            acc[0][2] = fmaf(a0, w.z, acc[0][2]);
            acc[0][3] = fmaf(a0, w.w, acc[0][3]);
            acc[1][0] = fmaf(a1, w.x, acc[1][0]);
            acc[1][1] = fmaf(a1, w.y, acc[1][1]);
            acc[1][2] = fmaf(a1, w.z, acc[1][2]);
            acc[1][3] = fmaf(a1, w.w, acc[1][3]);
            acc[2][0] = fmaf(a2, w.x, acc[2][0]);
            acc[2][1] = fmaf(a2, w.y, acc[2][1]);
            acc[2][2] = fmaf(a2, w.z, acc[2][2]);
            acc[2][3] = fmaf(a2, w.w, acc[2][3]);
            acc[3][0] = fmaf(a3, w.x, acc[3][0]);
            acc[3][1] = fmaf(a3, w.y, acc[3][1]);
            acc[3][2] = fmaf(a3, w.z, acc[3][2]);
            acc[3][3] = fmaf(a3, w.w, acc[3][3]);
        }
    }

    // ---- epilogue: float4 stores, full coverage of 32x128 tile ----
    #pragma unroll
    for (int i = 0; i < 4; i++) {
        float4 v = make_float4(acc[i][0], acc[i][1], acc[i][2], acc[i][3]);
        *(float4*)(out + (size_t)(n0 + r0 + i) * COUT + o0) = v;
    }
}

extern "C" void kernel_launch(void* const* d_in, const int* in_sizes, int n_in,
                              void* d_out, int out_size) {
    const float* query   = (const float*)d_in[0];
    const float* support = (const float*)d_in[1];
    const int*   nidx    = (const int*)d_in[2];
    const float* feats   = (const float*)d_in[3];
    const float* W       = (const float*)d_in[4];
    const float* kp      = (const float*)d_in[5];
    float* out = (float*)d_out;

    const int N = in_sizes[0] / 3;           // 16384
    const int smem_bytes = (QTILE*KN*CIN + QTILE*KN*16 + QTILE*CIN +
                            CIN*COUT + 48 + 96) * 4 + QTILE*KN * 4;

    cudaFuncSetAttribute(kpconv_kernel,
                         cudaFuncAttributeMaxDynamicSharedMemorySize, smem_bytes);
    kpconv_kernel<<<N / QTILE, NTHREADS, smem_bytes>>>(
        query, support, nidx, feats, W, kp, out);
}

// round 3
// speedup vs baseline: 1.2223x; 1.2223x over previous
#include <cuda_runtime.h>

#define QTILE 32
#define KN 16
#define NP 15
#define CIN 64
#define COUT 128
#define NT 256
#define AGG_LD 964   // padded row (floats): 16B-aligned rows, even bank spread

typedef unsigned long long u64;

__device__ __forceinline__ u64 pack2(float lo, float hi) {
    u64 r; asm("mov.b64 %0, {%1, %2};" : "=l"(r) : "f"(lo), "f"(hi)); return r;
}
// d = a * b + d   (packed 2x fp32, bit-exact vs two fmaf)
__device__ __forceinline__ void fma2(u64 &d, u64 a, u64 b) {
    asm("fma.rn.f32x2 %0, %1, %2, %3;" : "=l"(d) : "l"(a), "l"(b), "l"(d));
}

// smem (floats): s_agg 32*964=30848 | s_w 2*64*128=16384 | s_infl 32*16*16=8192
//                s_kp 48 | s_q 96 | s_nidx 512 ints  => 224,320 bytes total
__global__ __launch_bounds__(NT, 1)
void kpconv_kernel(const float* __restrict__ query,
                   const float* __restrict__ support,
                   const int*   __restrict__ nidx,
                   const float* __restrict__ feats,
                   const float* __restrict__ W,
                   const float* __restrict__ kp,
                   float* __restrict__ out)
{
    extern __shared__ float smem[];
    float* s_agg  = smem;                        // 32 x 964
    float* s_w    = s_agg + QTILE * AGG_LD;      // double buffer 64x128
    float* s_infl = s_w + 2 * CIN * COUT;        // [q][k][16]
    float* s_kp   = s_infl + QTILE * KN * 16;
    float* s_q    = s_kp + 48;
    int*   s_nidx = (int*)(s_q + 96);

    const int tid = threadIdx.x;
    const int n0  = blockIdx.x * QTILE;

    // ---- stage 0: indices, kernel points, query coords ----
    for (int i = tid; i < QTILE * KN; i += NT)
        s_nidx[i] = nidx[n0 * KN + i];
    if (tid < NP * 3)    s_kp[tid] = kp[tid];
    if (tid < QTILE * 3) s_q[tid]  = query[n0 * 3 + tid];
    __syncthreads();

    // ---- stage 1: influences infl[q][k][p] ----
    for (int pair = tid; pair < QTILE * KN; pair += NT) {
        int qq = pair >> 4;
        int m  = s_nidx[pair];
        float rx = support[m * 3 + 0] - s_q[qq * 3 + 0];
        float ry = support[m * 3 + 1] - s_q[qq * 3 + 1];
        float rz = support[m * 3 + 2] - s_q[qq * 3 + 2];
        #pragma unroll
        for (int p = 0; p < NP; p++) {
            float dx = rx - s_kp[p * 3 + 0];
            float dy = ry - s_kp[p * 3 + 1];
            float dz = rz - s_kp[p * 3 + 2];
            float d  = sqrtf(fmaf(dx, dx, fmaf(dy, dy, dz * dz)));
            s_infl[pair * 16 + p] = fmaxf(1.0f - d, 0.0f);
        }
        s_infl[pair * 16 + 15] = 0.0f;
    }
    __syncthreads();

    // ---- phase A: register aggregation for ALL p in one pass ----
    // thread -> (q = tid>>3, channels cc..cc+7); 15 x 4 packed accumulators
    const int q  = tid >> 3;
    const int cc = (tid & 7) << 3;
    u64 agg[NP][4];
    #pragma unroll
    for (int p = 0; p < NP; p++) {
        agg[p][0] = 0ULL; agg[p][1] = 0ULL; agg[p][2] = 0ULL; agg[p][3] = 0ULL;
    }

    #pragma unroll
    for (int k = 0; k < KN; k++) {
        int m = s_nidx[q * KN + k];
        const float4* fp = (const float4*)(feats + (size_t)m * CIN + cc);
        float4 f0 = __ldg(fp), f1 = __ldg(fp + 1);
        u64 fx0 = pack2(f0.x, f0.y), fx1 = pack2(f0.z, f0.w);
        u64 fx2 = pack2(f1.x, f1.y), fx3 = pack2(f1.z, f1.w);
        const float* ib = s_infl + (q * KN + k) * 16;
        float4 i0 = *(const float4*)(ib + 0);
        float4 i1 = *(const float4*)(ib + 4);
        float4 i2 = *(const float4*)(ib + 8);
        float4 i3 = *(const float4*)(ib + 12);
        float iv[16] = { i0.x,i0.y,i0.z,i0.w, i1.x,i1.y,i1.z,i1.w,
                         i2.x,i2.y,i2.z,i2.w, i3.x,i3.y,i3.z,i3.w };
        #pragma unroll
        for (int p = 0; p < NP; p++) {
            u64 ip = pack2(iv[p], iv[p]);
            fma2(agg[p][0], ip, fx0);
            fma2(agg[p][1], ip, fx1);
            fma2(agg[p][2], ip, fx2);
            fma2(agg[p][3], ip, fx3);
        }
    }

    // prefetch W chunk 0 while agg stores drain
    float4 wr[8];
    {
        const float4* src = (const float4*)W;
        #pragma unroll
        for (int j = 0; j < 8; j++) wr[j] = __ldg(src + tid + j * NT);
    }

    // store stacked agg: s_agg[q][p*64 + c]
    {
        float* dst = s_agg + q * AGG_LD + cc;
        #pragma unroll
        for (int p = 0; p < NP; p++) {
            #pragma unroll
            for (int j = 0; j < 4; j++)
                *(u64*)(dst + p * CIN + 2 * j) = agg[p][j];
        }
    }

    // store W chunk 0
    {
        float4* dst = (float4*)s_w;
        #pragma unroll
        for (int j = 0; j < 8; j++) dst[tid + j * NT] = wr[j];
    }
    __syncthreads();

    // ---- phase B: GEMM out[32x128] = s_agg[32x960] @ W[960x128] ----
    // lane = row, warp = 16-col group: a = conflict-free LDS.128,
    // w = warp-uniform broadcast LDS.128s
    const int lane = tid & 31;
    const int o0   = (tid >> 5) << 4;
    u64 o[8];
    #pragma unroll
    for (int j = 0; j < 8; j++) o[j] = 0ULL;

    for (int p = 0; p < NP; p++) {
        const float* wb = s_w + (p & 1) * (CIN * COUT);

        // prefetch next W chunk into regs (hidden under GEMM math)
        if (p < NP - 1) {
            const float4* src = (const float4*)(W + (size_t)(p + 1) * CIN * COUT);
            #pragma unroll
            for (int j = 0; j < 8; j++) wr[j] = __ldg(src + tid + j * NT);
        }

        const float* ar = s_agg + lane * AGG_LD + p * CIN;
        #pragma unroll 4
        for (int c4 = 0; c4 < CIN / 4; c4++) {
            float4 av = *(const float4*)(ar + c4 * 4);
            float avf[4] = { av.x, av.y, av.z, av.w };
            #pragma unroll
            for (int e = 0; e < 4; e++) {
                int c = c4 * 4 + e;
                u64 aa = pack2(avf[e], avf[e]);
                const ulonglong2* wrow = (const ulonglong2*)(wb + c * COUT + o0);
                ulonglong2 w01 = wrow[0], w23 = wrow[1];
                ulonglong2 w45 = wrow[2], w67 = wrow[3];
                fma2(o[0], aa, w01.x);
                fma2(o[1], aa, w01.y);
                fma2(o[2], aa, w23.x);
                fma2(o[3], aa, w23.y);
                fma2(o[4], aa, w45.x);
                fma2(o[5], aa, w45.y);
                fma2(o[6], aa, w67.x);
                fma2(o[7], aa, w67.y);
            }
        }
        __syncthreads();
        if (p < NP - 1) {
            float4* dst = (float4*)(s_w + ((p + 1) & 1) * (CIN * COUT));
            #pragma unroll
            for (int j = 0; j < 8; j++) dst[tid + j * NT] = wr[j];
            __syncthreads();
        }
    }

    // ---- epilogue: 16 floats per thread, 4x STG.128 ----
    float* orow = out + (size_t)(n0 + lane) * COUT + o0;
    #pragma unroll
    for (int j = 0; j < 4; j++) {
        ulonglong2 v;
        v.x = o[2 * j];
        v.y = o[2 * j + 1];
        *(ulonglong2*)(orow + 4 * j) = v;
    }
}

extern "C" void kernel_launch(void* const* d_in, const int* in_sizes, int n_in,
                              void* d_out, int out_size) {
    const float* query   = (const float*)d_in[0];
    const float* support = (const float*)d_in[1];
    const int*   nidx    = (const int*)d_in[2];
    const float* feats   = (const float*)d_in[3];
    const float* W       = (const float*)d_in[4];
    const float* kp      = (const float*)d_in[5];
    float* out = (float*)d_out;

    const int N = in_sizes[0] / 3;   // 16384
    const int smem_bytes = (QTILE * AGG_LD + 2 * CIN * COUT + QTILE * KN * 16 +
                            48 + 96) * 4 + QTILE * KN * 4;

    cudaFuncSetAttribute(kpconv_kernel,
                         cudaFuncAttributeMaxDynamicSharedMemorySize, smem_bytes);
    kpconv_kernel<<<N / QTILE, NT, smem_bytes>>>(
        query, support, nidx, feats, W, kp, out);
}

// round 5
// speedup vs baseline: 3.6486x; 2.9850x over previous
#include <cuda_runtime.h>
#include <cuda_bf16.h>
#include <cstdint>

#define NTOT 16384
#define KN   16
#define NP   15
#define CIN  64
#define COUT 128
#define KTOT (NP * CIN)        // 960

// ---------------- global scratch (allowed: __device__ arrays) ----------------
__device__ __nv_bfloat16 g_Ahi[(size_t)NTOT * KTOT];   // [n][k] k-major
__device__ __nv_bfloat16 g_Alo[(size_t)NTOT * KTOT];
__device__ __nv_bfloat16 g_Bhi[COUT * KTOT];           // [cout][k] k-major (= W^T)
__device__ __nv_bfloat16 g_Blo[COUT * KTOT];

typedef unsigned long long u64;
typedef unsigned int u32;

__device__ __forceinline__ u64 pack2(float lo, float hi) {
    u64 r; asm("mov.b64 %0, {%1, %2};" : "=l"(r) : "f"(lo), "f"(hi)); return r;
}
__device__ __forceinline__ void unpack2(u64 v, float &lo, float &hi) {
    asm("mov.b64 {%0, %1}, %2;" : "=f"(lo), "=f"(hi) : "l"(v));
}
__device__ __forceinline__ void fma2(u64 &d, u64 a, u64 b) {
    asm("fma.rn.f32x2 %0, %1, %2, %3;" : "=l"(d) : "l"(a), "l"(b), "l"(d));
}
__device__ __forceinline__ u32 bf16pk(float a, float b) {
    __nv_bfloat16 ha = __float2bfloat16_rn(a), hb = __float2bfloat16_rn(b);
    unsigned short ua = *reinterpret_cast<unsigned short*>(&ha);
    unsigned short ub = *reinterpret_cast<unsigned short*>(&hb);
    return (u32)ua | ((u32)ub << 16);
}
__device__ __forceinline__ u32 smem_u32(const void* p) {
    u32 a; asm("{ .reg .u64 t; cvta.to.shared.u64 t, %1; cvt.u32.u64 %0, t; }"
               : "=r"(a) : "l"(p));
    return a;
}
__device__ __forceinline__ void ldmx4(u32* r, u32 addr) {
    asm volatile("ldmatrix.sync.aligned.m8n8.x4.shared.b16 {%0,%1,%2,%3}, [%4];"
                 : "=r"(r[0]), "=r"(r[1]), "=r"(r[2]), "=r"(r[3]) : "r"(addr));
}
__device__ __forceinline__ void mma_bf16(float* d, const u32* a, const u32* b) {
    asm volatile("mma.sync.aligned.m16n8k16.row.col.f32.bf16.bf16.f32 "
                 "{%0,%1,%2,%3}, {%4,%5,%6,%7}, {%8,%9}, {%0,%1,%2,%3};"
                 : "+f"(d[0]), "+f"(d[1]), "+f"(d[2]), "+f"(d[3])
                 : "r"(a[0]), "r"(a[1]), "r"(a[2]), "r"(a[3]),
                   "r"(b[0]), "r"(b[1]));
}

// ================= kernel 0: split/transpose W =================
__global__ void k0_wsplit(const float* __restrict__ W) {
    int idx = blockIdx.x * blockDim.x + threadIdx.x;
    if (idx >= COUT * KTOT) return;
    int n = idx / KTOT;
    int k = idx - n * KTOT;
    int p = k >> 6, cin = k & 63;
    float w = W[p * CIN * COUT + cin * COUT + n];
    __nv_bfloat16 hi = __float2bfloat16_rn(w);
    float lof = w - __bfloat162float(hi);
    g_Bhi[idx] = hi;
    g_Blo[idx] = __float2bfloat16_rn(lof);
}

// ================= kernel 1: gather + influence + aggregation =================
#define Q1 16
#define NT1 256
__global__ __launch_bounds__(NT1)
void k1_agg(const float* __restrict__ query,
            const float* __restrict__ support,
            const int*   __restrict__ nidx,
            const float* __restrict__ feats,
            const float* __restrict__ kp)
{
    __shared__ float s_infl[Q1 * KN * 16];
    __shared__ float s_kp[48];
    __shared__ float s_q[Q1 * 3];
    __shared__ int   s_nidx[Q1 * KN];

    const int tid = threadIdx.x;
    const int n0  = blockIdx.x * Q1;

    if (tid < Q1 * KN)  s_nidx[tid] = nidx[n0 * KN + tid];
    if (tid < NP * 3)   s_kp[tid]   = kp[tid];
    if (tid < Q1 * 3)   s_q[tid]    = query[n0 * 3 + tid];
    __syncthreads();

    {
        int pair = tid;
        int qq = pair >> 4;
        int m  = s_nidx[pair];
        float rx = support[m * 3 + 0] - s_q[qq * 3 + 0];
        float ry = support[m * 3 + 1] - s_q[qq * 3 + 1];
        float rz = support[m * 3 + 2] - s_q[qq * 3 + 2];
        #pragma unroll
        for (int p = 0; p < NP; p++) {
            float dx = rx - s_kp[p * 3 + 0];
            float dy = ry - s_kp[p * 3 + 1];
            float dz = rz - s_kp[p * 3 + 2];
            float d  = sqrtf(fmaf(dx, dx, fmaf(dy, dy, dz * dz)));
            s_infl[pair * 16 + p] = fmaxf(1.0f - d, 0.0f);
        }
        s_infl[pair * 16 + 15] = 0.0f;
    }
    __syncthreads();

    const int q  = tid >> 4;
    const int ch = (tid & 15) << 2;

    u64 acc[NP][2];
    #pragma unroll
    for (int p = 0; p < NP; p++) { acc[p][0] = 0ULL; acc[p][1] = 0ULL; }

    #pragma unroll
    for (int k = 0; k < KN; k++) {
        int m = s_nidx[q * KN + k];
        float4 f = __ldg((const float4*)(feats + (size_t)m * CIN + ch));
        u64 fx = pack2(f.x, f.y), fy = pack2(f.z, f.w);
        const float* ib = s_infl + (q * KN + k) * 16;
        float4 i0 = *(const float4*)(ib + 0);
        float4 i1 = *(const float4*)(ib + 4);
        float4 i2 = *(const float4*)(ib + 8);
        float4 i3 = *(const float4*)(ib + 12);
        float iv[16] = { i0.x,i0.y,i0.z,i0.w, i1.x,i1.y,i1.z,i1.w,
                         i2.x,i2.y,i2.z,i2.w, i3.x,i3.y,i3.z,i3.w };
        #pragma unroll
        for (int p = 0; p < NP; p++) {
            u64 ip = pack2(iv[p], iv[p]);
            fma2(acc[p][0], ip, fx);
            fma2(acc[p][1], ip, fy);
        }
    }

    const size_t rowbase = (size_t)(n0 + q) * KTOT + ch;
    #pragma unroll
    for (int p = 0; p < NP; p++) {
        float a0, a1, a2, a3;
        unpack2(acc[p][0], a0, a1);
        unpack2(acc[p][1], a2, a3);
        __nv_bfloat16 h0 = __float2bfloat16_rn(a0);
        __nv_bfloat16 h1 = __float2bfloat16_rn(a1);
        __nv_bfloat16 h2 = __float2bfloat16_rn(a2);
        __nv_bfloat16 h3 = __float2bfloat16_rn(a3);
        float l0 = a0 - __bfloat162float(h0);
        float l1 = a1 - __bfloat162float(h1);
        float l2 = a2 - __bfloat162float(h2);
        float l3 = a3 - __bfloat162float(h3);
        unsigned short u0 = *reinterpret_cast<unsigned short*>(&h0);
        unsigned short u1 = *reinterpret_cast<unsigned short*>(&h1);
        unsigned short u2 = *reinterpret_cast<unsigned short*>(&h2);
        unsigned short u3 = *reinterpret_cast<unsigned short*>(&h3);
        uint2 vh = make_uint2((u32)u0 | ((u32)u1 << 16), (u32)u2 | ((u32)u3 << 16));
        uint2 vl = make_uint2(bf16pk(l0, l1), bf16pk(l2, l3));
        *(uint2*)(g_Ahi + rowbase + p * CIN) = vh;
        *(uint2*)(g_Alo + rowbase + p * CIN) = vl;
    }
}

// ================= kernel 2: mma.sync bf16x3 GEMM =================
// D[16384 x 128] = Ahi*Bhi + Ahi*Blo + Alo*Bhi ; M-tile 128, N=128, K=960.
// smem: 2 buffers x 4 tiles x [128 rows x 128B] = 131072 bytes.
#define NT2 256
#define NCHUNK 15
#define TILEB 16384
#define BUFB  (4 * TILEB)

__global__ __launch_bounds__(NT2, 1)
void k2_gemm(float* __restrict__ out)
{
    extern __shared__ char smem[];
    const u32 sb = smem_u32(smem);
    const int tid  = threadIdx.x;
    const int wid  = tid >> 5;
    const int lane = tid & 31;
    const int wm   = wid >> 2;       // 0..1  (M groups of 64)
    const int wn   = wid & 3;        // 0..3  (N groups of 32)
    const int m0   = blockIdx.x * 128;

    const __nv_bfloat16* srcs[4] = { g_Ahi, g_Alo, g_Bhi, g_Blo };

    // ldmatrix per-thread addressing (swizzle: row*128 + (o ^ (row&7)*16))
    const int a_row  = wm * 64 + (lane & 7) + ((lane >> 3) & 1) * 8;  // + mi*16
    const int a_bh   = ((lane >> 4) & 1) * 16;
    const u32 a_mask = (u32)((a_row & 7) * 16);
    const int b_row  = wn * 32 + (lane & 7) + ((lane >> 4) & 1) * 8;  // + nj*16
    const int b_bh   = ((lane >> 3) & 1) * 16;
    const u32 b_mask = (u32)((b_row & 7) * 16);

    float acc[4][4][4];
    #pragma unroll
    for (int mi = 0; mi < 4; mi++)
        #pragma unroll
        for (int ni = 0; ni < 4; ni++)
            #pragma unroll
            for (int e = 0; e < 4; e++) acc[mi][ni][e] = 0.0f;

    // ---- async load of one chunk into buffer (c&1) ----
    auto load_chunk = [&](int c) {
        u32 dstb = sb + (u32)(c & 1) * BUFB;
        #pragma unroll
        for (int j = 0; j < 16; j++) {
            int idx = tid + j * NT2;              // 0..4095
            int t    = idx >> 10;
            int win  = idx & 1023;
            int row  = win >> 3;
            int c16  = win & 7;
            int rb   = (t < 2) ? m0 : 0;
            const __nv_bfloat16* src = srcs[t] + (size_t)(rb + row) * KTOT
                                       + c * 64 + c16 * 8;
            u32 dst = dstb + (u32)t * TILEB
                    + (u32)(row * 128 + ((c16 * 16) ^ ((row & 7) * 16)));
            asm volatile("cp.async.cg.shared.global [%0], [%1], 16;"
                         :: "r"(dst), "l"(src) : "memory");
        }
        asm volatile("cp.async.commit_group;" ::: "memory");
    };

    load_chunk(0);

    for (int c = 0; c < NCHUNK; c++) {
        if (c + 1 < NCHUNK) {
            load_chunk(c + 1);
            asm volatile("cp.async.wait_group 1;" ::: "memory");
        } else {
            asm volatile("cp.async.wait_group 0;" ::: "memory");
        }
        __syncthreads();

        const u32 bufb = sb + (u32)(c & 1) * BUFB;
        const u32 aBase   = bufb + (u32)(a_row * 128);
        const u32 bHiBase = bufb + 2 * TILEB + (u32)(b_row * 128);

        #pragma unroll
        for (int ks = 0; ks < 4; ks++) {
            const u32 aOff = (u32)((ks * 32 + a_bh)) ^ a_mask;
            const u32 bOff = (u32)((ks * 32 + b_bh)) ^ b_mask;

            u32 bhi[8], blo[8];
            #pragma unroll
            for (int nj = 0; nj < 2; nj++) {
                u32 ba = bHiBase + (u32)(nj * 16 * 128) + bOff;
                ldmx4(&bhi[nj * 4], ba);
                ldmx4(&blo[nj * 4], ba + TILEB);
            }
            #pragma unroll
            for (int mi = 0; mi < 4; mi++) {
                u32 ahi[4], alo[4];
                u32 aa = aBase + (u32)(mi * 16 * 128) + aOff;
                ldmx4(ahi, aa);
                ldmx4(alo, aa + TILEB);
                #pragma unroll
                for (int ni = 0; ni < 4; ni++)
                    mma_bf16(acc[mi][ni], ahi, &bhi[(ni >> 1) * 4 + (ni & 1) * 2]);
                #pragma unroll
                for (int ni = 0; ni < 4; ni++)
                    mma_bf16(acc[mi][ni], ahi, &blo[(ni >> 1) * 4 + (ni & 1) * 2]);
                #pragma unroll
                for (int ni = 0; ni < 4; ni++)
                    mma_bf16(acc[mi][ni], alo, &bhi[(ni >> 1) * 4 + (ni & 1) * 2]);
            }
        }
        __syncthreads();
    }

    // ---- epilogue ----
    #pragma unroll
    for (int mi = 0; mi < 4; mi++) {
        int row = m0 + wm * 64 + mi * 16 + (lane >> 2);
        #pragma unroll
        for (int ni = 0; ni < 4; ni++) {
            int col = wn * 32 + ni * 8 + (lane & 3) * 2;
            *(float2*)(out + (size_t)row * COUT + col) =
                make_float2(acc[mi][ni][0], acc[mi][ni][1]);
            *(float2*)(out + (size_t)(row + 8) * COUT + col) =
                make_float2(acc[mi][ni][2], acc[mi][ni][3]);
        }
    }
}

// ================= launch =================
extern "C" void kernel_launch(void* const* d_in, const int* in_sizes, int n_in,
                              void* d_out, int out_size) {
    const float* query   = (const float*)d_in[0];
    const float* support = (const float*)d_in[1];
    const int*   nidx    = (const int*)d_in[2];
    const float* feats   = (const float*)d_in[3];
    const float* W       = (const float*)d_in[4];
    const float* kp      = (const float*)d_in[5];
    float* out = (float*)d_out;

    k0_wsplit<<<(COUT * KTOT + 255) / 256, 256>>>(W);
    k1_agg<<<NTOT / Q1, NT1>>>(query, support, nidx, feats, kp);

    const int smem2 = 2 * BUFB;   // 131072
    cudaFuncSetAttribute(k2_gemm, cudaFuncAttributeMaxDynamicSharedMemorySize, smem2);
    k2_gemm<<<NTOT / 128, NT2, smem2>>>(out);
}

// round 6
// speedup vs baseline: 4.6607x; 1.2774x over previous
#include <cuda_runtime.h>
#include <cuda_fp16.h>
#include <cstdint>

#define NTOT 16384
#define KN   16
#define NP   15
#define CIN  64
#define COUT 128
#define KTOT (NP * CIN)        // 960

// ---------------- global scratch (allowed: __device__ arrays) ----------------
__device__ __half g_A[(size_t)NTOT * KTOT];     // [n][k] k-major, fp16
__device__ __half g_Bhi[COUT * KTOT];           // [cout][k] k-major (= W^T) hi
__device__ __half g_Blo[COUT * KTOT];           // residual lo

typedef unsigned long long u64;
typedef unsigned int u32;

__device__ __forceinline__ u64 pack2(float lo, float hi) {
    u64 r; asm("mov.b64 %0, {%1, %2};" : "=l"(r) : "f"(lo), "f"(hi)); return r;
}
__device__ __forceinline__ void unpack2(u64 v, float &lo, float &hi) {
    asm("mov.b64 {%0, %1}, %2;" : "=f"(lo), "=f"(hi) : "l"(v));
}
__device__ __forceinline__ void fma2(u64 &d, u64 a, u64 b) {
    asm("fma.rn.f32x2 %0, %1, %2, %3;" : "=l"(d) : "l"(a), "l"(b), "l"(d));
}
__device__ __forceinline__ u32 h2pk(float a, float b) {
    __half ha = __float2half_rn(a), hb = __float2half_rn(b);
    unsigned short ua = *reinterpret_cast<unsigned short*>(&ha);
    unsigned short ub = *reinterpret_cast<unsigned short*>(&hb);
    return (u32)ua | ((u32)ub << 16);
}
__device__ __forceinline__ u32 smem_u32(const void* p) {
    u32 a; asm("{ .reg .u64 t; cvta.to.shared.u64 t, %1; cvt.u32.u64 %0, t; }"
               : "=r"(a) : "l"(p));
    return a;
}
__device__ __forceinline__ void ldmx4(u32* r, u32 addr) {
    asm volatile("ldmatrix.sync.aligned.m8n8.x4.shared.b16 {%0,%1,%2,%3}, [%4];"
                 : "=r"(r[0]), "=r"(r[1]), "=r"(r[2]), "=r"(r[3]) : "r"(addr));
}
__device__ __forceinline__ void mma_f16(float* d, const u32* a, const u32* b) {
    asm volatile("mma.sync.aligned.m16n8k16.row.col.f32.f16.f16.f32 "
                 "{%0,%1,%2,%3}, {%4,%5,%6,%7}, {%8,%9}, {%0,%1,%2,%3};"
                 : "+f"(d[0]), "+f"(d[1]), "+f"(d[2]), "+f"(d[3])
                 : "r"(a[0]), "r"(a[1]), "r"(a[2]), "r"(a[3]),
                   "r"(b[0]), "r"(b[1]));
}

// ====== kernel 1: gather + influence + aggregation (+ fused W-split) ======
#define Q1 16
#define NT1 256
__global__ __launch_bounds__(NT1)
void k1_agg(const float* __restrict__ query,
            const float* __restrict__ support,
            const int*   __restrict__ nidx,
            const float* __restrict__ feats,
            const float* __restrict__ kp,
            const float* __restrict__ W)
{
    __shared__ float s_infl[Q1 * KN * 16];
    __shared__ float s_kp[48];
    __shared__ float s_q[Q1 * 3];
    __shared__ int   s_nidx[Q1 * KN];

    const int tid = threadIdx.x;
    const int n0  = blockIdx.x * Q1;

    if (tid < Q1 * KN)  s_nidx[tid] = nidx[n0 * KN + tid];
    if (tid < NP * 3)   s_kp[tid]   = kp[tid];
    if (tid < Q1 * 3)   s_q[tid]    = query[n0 * 3 + tid];
    __syncthreads();

    // influences: one (q,k) pair per thread
    {
        int pair = tid;
        int qq = pair >> 4;
        int m  = s_nidx[pair];
        float rx = support[m * 3 + 0] - s_q[qq * 3 + 0];
        float ry = support[m * 3 + 1] - s_q[qq * 3 + 1];
        float rz = support[m * 3 + 2] - s_q[qq * 3 + 2];
        #pragma unroll
        for (int p = 0; p < NP; p++) {
            float dx = rx - s_kp[p * 3 + 0];
            float dy = ry - s_kp[p * 3 + 1];
            float dz = rz - s_kp[p * 3 + 2];
            float d  = sqrtf(fmaf(dx, dx, fmaf(dy, dy, dz * dz)));
            s_infl[pair * 16 + p] = fmaxf(1.0f - d, 0.0f);
        }
        s_infl[pair * 16 + 15] = 0.0f;
    }
    __syncthreads();

    const int q  = tid >> 4;
    const int ch = (tid & 15) << 2;

    u64 acc[NP][2];
    #pragma unroll
    for (int p = 0; p < NP; p++) { acc[p][0] = 0ULL; acc[p][1] = 0ULL; }

    #pragma unroll
    for (int k = 0; k < KN; k++) {
        int m = s_nidx[q * KN + k];
        float4 f = __ldg((const float4*)(feats + (size_t)m * CIN + ch));
        u64 fx = pack2(f.x, f.y), fy = pack2(f.z, f.w);
        const float* ib = s_infl + (q * KN + k) * 16;
        float4 i0 = *(const float4*)(ib + 0);
        float4 i1 = *(const float4*)(ib + 4);
        float4 i2 = *(const float4*)(ib + 8);
        float4 i3 = *(const float4*)(ib + 12);
        float iv[16] = { i0.x,i0.y,i0.z,i0.w, i1.x,i1.y,i1.z,i1.w,
                         i2.x,i2.y,i2.z,i2.w, i3.x,i3.y,i3.z,i3.w };
        #pragma unroll
        for (int p = 0; p < NP; p++) {
            u64 ip = pack2(iv[p], iv[p]);
            fma2(acc[p][0], ip, fx);
            fma2(acc[p][1], ip, fy);
        }
    }

    // store A as single fp16 (4 channels -> 8B uint2 per p)
    const size_t rowbase = (size_t)(n0 + q) * KTOT + ch;
    #pragma unroll
    for (int p = 0; p < NP; p++) {
        float a0, a1, a2, a3;
        unpack2(acc[p][0], a0, a1);
        unpack2(acc[p][1], a2, a3);
        uint2 v = make_uint2(h2pk(a0, a1), h2pk(a2, a3));
        *(uint2*)(g_A + rowbase + p * CIN) = v;
    }

    // ---- fused W-split: blocks 0..119 convert W -> Bhi/Blo fp16 ----
    if (blockIdx.x < 120) {
        int idx4 = blockIdx.x * NT1 + tid;     // 0..30719, 4 k-elems each
        int n  = idx4 / 240;
        int kq = idx4 - n * 240;
        int k  = kq * 4;
        int p  = k >> 6, cin = k & 63;
        const float* wp = W + p * CIN * COUT + cin * COUT + n;
        float w0 = __ldg(wp);
        float w1 = __ldg(wp + COUT);
        float w2 = __ldg(wp + 2 * COUT);
        float w3 = __ldg(wp + 3 * COUT);
        __half h0 = __float2half_rn(w0), h1 = __float2half_rn(w1);
        __half h2 = __float2half_rn(w2), h3 = __float2half_rn(w3);
        float l0 = w0 - __half2float(h0), l1 = w1 - __half2float(h1);
        float l2 = w2 - __half2float(h2), l3 = w3 - __half2float(h3);
        unsigned short u0 = *reinterpret_cast<unsigned short*>(&h0);
        unsigned short u1 = *reinterpret_cast<unsigned short*>(&h1);
        unsigned short u2 = *reinterpret_cast<unsigned short*>(&h2);
        unsigned short u3 = *reinterpret_cast<unsigned short*>(&h3);
        uint2 vh = make_uint2((u32)u0 | ((u32)u1 << 16), (u32)u2 | ((u32)u3 << 16));
        uint2 vl = make_uint2(h2pk(l0, l1), h2pk(l2, l3));
        *(uint2*)(g_Bhi + (size_t)n * KTOT + k) = vh;
        *(uint2*)(g_Blo + (size_t)n * KTOT + k) = vl;
    }
}

// ================= kernel 2: mma.sync fp16 x2 GEMM =================
// D[16384 x 128] = A*(Bhi+Blo) ; M-tile 128, N=128, K=960.
// smem: 2 buffers x 3 tiles x [128 rows x 128B] = 98304 bytes.
#define NT2 256
#define NCHUNK 15
#define TILEB 16384
#define BUFB  (3 * TILEB)

__global__ __launch_bounds__(NT2, 1)
void k2_gemm(float* __restrict__ out)
{
    extern __shared__ char smem[];
    const u32 sb = smem_u32(smem);
    const int tid  = threadIdx.x;
    const int wid  = tid >> 5;
    const int lane = tid & 31;
    const int wm   = wid >> 2;       // 0..1  (M groups of 64)
    const int wn   = wid & 3;        // 0..3  (N groups of 32)
    const int m0   = blockIdx.x * 128;

    const __half* srcs[3] = { g_A, g_Bhi, g_Blo };

    // ldmatrix per-thread addressing (swizzle: row*128 + (o ^ (row&7)*16))
    const int a_row  = wm * 64 + (lane & 7) + ((lane >> 3) & 1) * 8;  // + mi*16
    const int a_bh   = ((lane >> 4) & 1) * 16;
    const u32 a_mask = (u32)((a_row & 7) * 16);
    const int b_row  = wn * 32 + (lane & 7) + ((lane >> 4) & 1) * 8;  // + nj*16
    const int b_bh   = ((lane >> 3) & 1) * 16;
    const u32 b_mask = (u32)((b_row & 7) * 16);

    float acc[4][4][4];
    #pragma unroll
    for (int mi = 0; mi < 4; mi++)
        #pragma unroll
        for (int ni = 0; ni < 4; ni++)
            #pragma unroll
            for (int e = 0; e < 4; e++) acc[mi][ni][e] = 0.0f;

    // ---- async load of one chunk into buffer (c&1): 3 tiles ----
    auto load_chunk = [&](int c) {
        u32 dstb = sb + (u32)(c & 1) * BUFB;
        #pragma unroll
        for (int j = 0; j < 12; j++) {
            int idx = tid + j * NT2;              // 0..3071
            int t    = idx >> 10;                 // 0:A 1:Bhi 2:Blo
            int win  = idx & 1023;
            int row  = win >> 3;
            int c16  = win & 7;
            int rb   = (t == 0) ? m0 : 0;
            const __half* src = srcs[t] + (size_t)(rb + row) * KTOT
                                + c * 64 + c16 * 8;
            u32 dst = dstb + (u32)t * TILEB
                    + (u32)(row * 128 + ((c16 * 16) ^ ((row & 7) * 16)));
            asm volatile("cp.async.cg.shared.global [%0], [%1], 16;"
                         :: "r"(dst), "l"(src) : "memory");
        }
        asm volatile("cp.async.commit_group;" ::: "memory");
    };

    load_chunk(0);

    for (int c = 0; c < NCHUNK; c++) {
        if (c + 1 < NCHUNK) {
            load_chunk(c + 1);
            asm volatile("cp.async.wait_group 1;" ::: "memory");
        } else {
            asm volatile("cp.async.wait_group 0;" ::: "memory");
        }
        __syncthreads();

        const u32 bufb = sb + (u32)(c & 1) * BUFB;
        const u32 aBase   = bufb + (u32)(a_row * 128);
        const u32 bHiBase = bufb + TILEB + (u32)(b_row * 128);

        #pragma unroll
        for (int ks = 0; ks < 4; ks++) {
            const u32 aOff = (u32)((ks * 32 + a_bh)) ^ a_mask;
            const u32 bOff = (u32)((ks * 32 + b_bh)) ^ b_mask;

            u32 bhi[8], blo[8];
            #pragma unroll
            for (int nj = 0; nj < 2; nj++) {
                u32 ba = bHiBase + (u32)(nj * 16 * 128) + bOff;
                ldmx4(&bhi[nj * 4], ba);
                ldmx4(&blo[nj * 4], ba + TILEB);
            }
            #pragma unroll
            for (int mi = 0; mi < 4; mi++) {
                u32 a[4];
                ldmx4(a, aBase + (u32)(mi * 16 * 128) + aOff);
                #pragma unroll
                for (int ni = 0; ni < 4; ni++)
                    mma_f16(acc[mi][ni], a, &bhi[(ni >> 1) * 4 + (ni & 1) * 2]);
                #pragma unroll
                for (int ni = 0; ni < 4; ni++)
                    mma_f16(acc[mi][ni], a, &blo[(ni >> 1) * 4 + (ni & 1) * 2]);
            }
        }
        __syncthreads();
    }

    // ---- epilogue ----
    #pragma unroll
    for (int mi = 0; mi < 4; mi++) {
        int row = m0 + wm * 64 + mi * 16 + (lane >> 2);
        #pragma unroll
        for (int ni = 0; ni < 4; ni++) {
            int col = wn * 32 + ni * 8 + (lane & 3) * 2;
            *(float2*)(out + (size_t)row * COUT + col) =
                make_float2(acc[mi][ni][0], acc[mi][ni][1]);
            *(float2*)(out + (size_t)(row + 8) * COUT + col) =
                make_float2(acc[mi][ni][2], acc[mi][ni][3]);
        }
    }
}

// ================= launch =================
extern "C" void kernel_launch(void* const* d_in, const int* in_sizes, int n_in,
                              void* d_out, int out_size) {
    const float* query   = (const float*)d_in[0];
    const float* support = (const float*)d_in[1];
    const int*   nidx    = (const int*)d_in[2];
    const float* feats   = (const float*)d_in[3];
    const float* W       = (const float*)d_in[4];
    const float* kp      = (const float*)d_in[5];
    float* out = (float*)d_out;

    k1_agg<<<NTOT / Q1, NT1>>>(query, support, nidx, feats, kp, W);

    const int smem2 = 2 * BUFB;   // 98304
    cudaFuncSetAttribute(k2_gemm, cudaFuncAttributeMaxDynamicSharedMemorySize, smem2);
    k2_gemm<<<NTOT / 128, NT2, smem2>>>(out);
}